// round 9
// baseline (speedup 1.0000x reference)
#include <cuda_runtime.h>
#include <cuda_bf16.h>
#include <cstdint>

// out[row, i, e] = x[row, i] * W[i, e] + b[i, e]
// rows = 16384, i in [0,200), e in [0,64).
//
// Round-8: final burst-length probe. 800-thread blocks write 25KB fully
// contiguous per iteration (vs 10KB in R6); grid 2x1024 = 2048 blocks gives
// near-uniform wave fill (6.9 waves of 296). Otherwise the proven structure:
// STG.E.256 .cs, W/b register-resident, thread-per-32B chunk, regs<=32.

#define N_NUM    200
#define E4       16                   // float4 per feature
#define COLS     (N_NUM * E4)         // 3200 float4 per row
#define CHUNKS   (COLS / 2)           // 1600 32B-chunks per row
#define N_ROWS   16384
#define TPB      800                  // 25 warps -> 25KB contiguous per iter
#define CBLKS    (CHUNKS / TPB)       // 2 column blocks
#define RPB      16                   // rows per block
#define RBLKS    (N_ROWS / RPB)       // 1024 row blocks
#define RUNROLL  4

__device__ __forceinline__ void stg256_cs(void* p, float4 a, float4 b)
{
    asm volatile(
        "st.global.cs.v8.b32 [%0], {%1,%2,%3,%4,%5,%6,%7,%8};"
        :: "l"(p),
           "r"(__float_as_uint(a.x)), "r"(__float_as_uint(a.y)),
           "r"(__float_as_uint(a.z)), "r"(__float_as_uint(a.w)),
           "r"(__float_as_uint(b.x)), "r"(__float_as_uint(b.y)),
           "r"(__float_as_uint(b.z)), "r"(__float_as_uint(b.w))
        : "memory");
}

__global__ __launch_bounds__(TPB, 2)   // 2x800 = 1600 thr/SM, regs<=32
void numproj_kernel(const float* __restrict__ x,
                    const float4* __restrict__ W4,
                    const float4* __restrict__ B4,
                    float4* __restrict__ out)
{
    const int c    = blockIdx.x * TPB + threadIdx.x;  // 32B chunk 0..1599
    const int j0   = 2 * c;                           // first float4 column
    const int i    = c >> 3;                          // feature 0..199
    const int row0 = blockIdx.y * RPB;

    // Per-column constants held in registers for all rows.
    const float4 w0 = __ldg(&W4[j0]);
    const float4 w1 = __ldg(&W4[j0 + 1]);
    const float4 b0 = __ldg(&B4[j0]);
    const float4 b1 = __ldg(&B4[j0 + 1]);

    const float* xp = x + (size_t)row0 * N_NUM + i;
    char* op = (char*)(out + (size_t)row0 * COLS + j0);
    const size_t row_bytes = (size_t)COLS * sizeof(float4);

    #pragma unroll 1
    for (int r = 0; r < RPB; r += RUNROLL) {
        float xv[RUNROLL];
        #pragma unroll
        for (int u = 0; u < RUNROLL; ++u)
            xv[u] = __ldg(xp + (size_t)u * N_NUM);

        #pragma unroll
        for (int u = 0; u < RUNROLL; ++u) {
            float4 o0, o1;
            o0.x = fmaf(xv[u], w0.x, b0.x);
            o0.y = fmaf(xv[u], w0.y, b0.y);
            o0.z = fmaf(xv[u], w0.z, b0.z);
            o0.w = fmaf(xv[u], w0.w, b0.w);
            o1.x = fmaf(xv[u], w1.x, b1.x);
            o1.y = fmaf(xv[u], w1.y, b1.y);
            o1.z = fmaf(xv[u], w1.z, b1.z);
            o1.w = fmaf(xv[u], w1.w, b1.w);
            stg256_cs(op + (size_t)u * row_bytes, o0, o1);
        }
        xp += (size_t)RUNROLL * N_NUM;
        op += (size_t)RUNROLL * row_bytes;
    }
}

extern "C" void kernel_launch(void* const* d_in, const int* in_sizes, int n_in,
                              void* d_out, int out_size)
{
    const float*  x  = (const float*) d_in[0];   // [16384, 200] f32
    const float4* W4 = (const float4*)d_in[1];   // [200, 64] f32 -> 3200 float4
    const float4* B4 = (const float4*)d_in[2];
    float4* out = (float4*)d_out;

    dim3 grid(CBLKS, RBLKS);   // 2 x 1024 = 2048 blocks
    numproj_kernel<<<grid, TPB>>>(x, W4, B4, out);
}

// round 10
// speedup vs baseline: 1.0151x; 1.0151x over previous
#include <cuda_runtime.h>
#include <cuda_bf16.h>
#include <cstdint>

// out[row, i, e] = x[row, i] * W[i, e] + b[i, e]
// rows = 16384, i in [0,200), e in [0,64).
//
// FINAL (session best, benched 131.2us): HBM write-roofline kernel.
//  - thread-per-32B output chunk, W/b held in registers for all rows
//  - STG.E.256 streaming stores (.cs), fully coalesced; 10KB contiguous
//    burst per block iteration (320 threads)
//  - x loads are warp-broadcast L2 hits, batched x4 for MLP
//  - regs capped at 32, no smem, no syncs
// Measured at 6.5 TB/s effective store throughput = practical HBM3e write
// ceiling (occupancy/policy/burst-length/width sweeps in R2-R8 all flat).

#define N_NUM    200
#define E4       16                   // float4 per feature
#define COLS     (N_NUM * E4)         // 3200 float4 per row
#define CHUNKS   (COLS / 2)           // 1600 32B-chunks per row
#define N_ROWS   16384
#define TPB      320                  // 10 warps -> 10KB contiguous per iter
#define CBLKS    (CHUNKS / TPB)       // 5 column blocks
#define RPB      16                   // rows per block
#define RBLKS    (N_ROWS / RPB)       // 1024 row blocks
#define RUNROLL  4

__device__ __forceinline__ void stg256_cs(void* p, float4 a, float4 b)
{
    asm volatile(
        "st.global.cs.v8.b32 [%0], {%1,%2,%3,%4,%5,%6,%7,%8};"
        :: "l"(p),
           "r"(__float_as_uint(a.x)), "r"(__float_as_uint(a.y)),
           "r"(__float_as_uint(a.z)), "r"(__float_as_uint(a.w)),
           "r"(__float_as_uint(b.x)), "r"(__float_as_uint(b.y)),
           "r"(__float_as_uint(b.z)), "r"(__float_as_uint(b.w))
        : "memory");
}

__global__ __launch_bounds__(TPB, 6)   // keep regs<=32
void numproj_kernel(const float* __restrict__ x,
                    const float4* __restrict__ W4,
                    const float4* __restrict__ B4,
                    float4* __restrict__ out)
{
    const int c    = blockIdx.x * TPB + threadIdx.x;  // 32B chunk 0..1599
    const int j0   = 2 * c;                           // first float4 column
    const int i    = c >> 3;                          // feature 0..199
    const int row0 = blockIdx.y * RPB;

    // Per-column constants held in registers for all rows.
    const float4 w0 = __ldg(&W4[j0]);
    const float4 w1 = __ldg(&W4[j0 + 1]);
    const float4 b0 = __ldg(&B4[j0]);
    const float4 b1 = __ldg(&B4[j0 + 1]);

    const float* xp = x + (size_t)row0 * N_NUM + i;
    char* op = (char*)(out + (size_t)row0 * COLS + j0);
    const size_t row_bytes = (size_t)COLS * sizeof(float4);

    #pragma unroll 1
    for (int r = 0; r < RPB; r += RUNROLL) {
        float xv[RUNROLL];
        #pragma unroll
        for (int u = 0; u < RUNROLL; ++u)
            xv[u] = __ldg(xp + (size_t)u * N_NUM);

        #pragma unroll
        for (int u = 0; u < RUNROLL; ++u) {
            float4 o0, o1;
            o0.x = fmaf(xv[u], w0.x, b0.x);
            o0.y = fmaf(xv[u], w0.y, b0.y);
            o0.z = fmaf(xv[u], w0.z, b0.z);
            o0.w = fmaf(xv[u], w0.w, b0.w);
            o1.x = fmaf(xv[u], w1.x, b1.x);
            o1.y = fmaf(xv[u], w1.y, b1.y);
            o1.z = fmaf(xv[u], w1.z, b1.z);
            o1.w = fmaf(xv[u], w1.w, b1.w);
            stg256_cs(op + (size_t)u * row_bytes, o0, o1);
        }
        xp += (size_t)RUNROLL * N_NUM;
        op += (size_t)RUNROLL * row_bytes;
    }
}

extern "C" void kernel_launch(void* const* d_in, const int* in_sizes, int n_in,
                              void* d_out, int out_size)
{
    const float*  x  = (const float*) d_in[0];   // [16384, 200] f32
    const float4* W4 = (const float4*)d_in[1];   // [200, 64] f32 -> 3200 float4
    const float4* B4 = (const float4*)d_in[2];
    float4* out = (float4*)d_out;

    dim3 grid(CBLKS, RBLKS);   // 5 x 1024 blocks
    numproj_kernel<<<grid, TPB>>>(x, W4, B4, out);
}